// round 11
// baseline (speedup 1.0000x reference)
#include <cuda_runtime.h>
#include <cuda_fp16.h>
#include <stdint.h>
#include <math.h>

#define BATCH 64
#define HID   1024
#define LEN   128

#define WSTG   4096            // W stage: 32 rows x 64 k fp16
#define VSTG   8192            // V stage: 64 rows x 64 k fp16
#define NSTAGES 32             // K=2048 in 64-chunks (0-15: W_ih seg, 16-31: W_hh seg)
#define NPIPE  8               // smem pipeline depth
#define CTA_WB ((size_t)NSTAGES * WSTG)     // 128KB per (layer, cta)
#define STGB   (WSTG + VSTG)   // 12288 bytes per smem stage

#define SMEM_ST0 1024
#define SMEM_GSM (SMEM_ST0 + NPIPE * STGB)  // 99328
#define GSM_STRIDE 68
#define SMEM_TOTAL (SMEM_GSM + 32 * GSM_STRIDE * 4)   // 108032

#define SWZ(x) ((x) ^ (((x) >> 3) & 0x70))

// ----------------- persistent device state (no runtime allocations) ---------
__device__ __align__(1024) char Wpack[2u * 128u * 131072u];   // 32MB
__device__ __align__(1024) char Vx[16 * VSTG];
__device__ __align__(1024) char V0[2][16 * VSTG];
__device__ __align__(1024) char V1[2][16 * VSTG];
__device__ float Cst[2][BATCH * HID];
__device__ float Bpack[2][4096];

// ----------------- PTX helpers ----------------------------------------------
__device__ __forceinline__ uint32_t smem_u32(const void* p) {
    uint32_t a;
    asm("{ .reg .u64 t; cvta.to.shared.u64 t, %1; cvt.u32.u64 %0, t; }" : "=r"(a) : "l"(p));
    return a;
}
#define MBAR_INIT(a, c) asm volatile("mbarrier.init.shared.b64 [%0], %1;" :: "r"(a), "r"(c) : "memory")
#define MBAR_EXPECT_TX(a, tx) asm volatile("mbarrier.arrive.expect_tx.shared.b64 _, [%0], %1;" :: "r"(a), "r"(tx) : "memory")
#define MBAR_ARRIVE(a) asm volatile("mbarrier.arrive.shared.b64 _, [%0];" :: "r"(a) : "memory")
#define MBAR_WAIT(addr, ph) do {                                              \
    uint32_t _m = (addr), _p = (ph), _d;                                      \
    asm volatile("{\n\t.reg .pred p;\n\t"                                     \
        "mbarrier.try_wait.parity.acquire.cta.shared::cta.b64 p, [%1], %2;\n\t" \
        "selp.b32 %0, 1, 0, p;\n\t}" : "=r"(_d) : "r"(_m), "r"(_p) : "memory"); \
    if (!_d) {                                                                \
        asm volatile("{\n\t.reg .pred P1;\n\t"                                \
            "WL%=:\n\t"                                                       \
            "mbarrier.try_wait.parity.acquire.cta.shared::cta.b64 P1, [%0], %1, 0x989680;\n\t" \
            "@P1 bra.uni WD%=;\n\t"                                           \
            "bra.uni WL%=;\n\t"                                               \
            "WD%=:\n\t}" :: "r"(_m), "r"(_p) : "memory");                     \
    } } while (0)

#define BULK_G2S(dst, src, bytes, mbar)                                       \
    asm volatile("cp.async.bulk.shared::cta.global.mbarrier::complete_tx::bytes [%0], [%1], %2, [%3];" \
        :: "r"(dst), "l"(src), "r"(bytes), "r"(mbar) : "memory")

__device__ __forceinline__ void ldmx4(uint32_t* r, uint32_t addr) {
    asm volatile("ldmatrix.sync.aligned.m8n8.x4.shared.b16 {%0,%1,%2,%3}, [%4];"
        : "=r"(r[0]), "=r"(r[1]), "=r"(r[2]), "=r"(r[3]) : "r"(addr));
}
__device__ __forceinline__ void mma16816(float* d, const uint32_t* a, const uint32_t* b) {
    asm volatile("mma.sync.aligned.m16n8k16.row.col.f32.f16.f16.f32 "
        "{%0,%1,%2,%3}, {%4,%5,%6,%7}, {%8,%9}, {%0,%1,%2,%3};"
        : "+f"(d[0]), "+f"(d[1]), "+f"(d[2]), "+f"(d[3])
        : "r"(a[0]), "r"(a[1]), "r"(a[2]), "r"(a[3]), "r"(b[0]), "r"(b[1]));
}
__device__ __forceinline__ float sigm(float x) { return 1.0f / (1.0f + __expf(-x)); }
__device__ __forceinline__ float tanh_f(float x) {
    float ax = fabsf(x);
    float t  = __expf(-2.0f * ax);
    return copysignf((1.0f - t) / (1.0f + t), x);
}

// ----------------- one-time (per replay) weight packing ----------------------
// CTA bid owns units u = bid*8+j; tile row tr = gate*8+j (32 rows). Stage =
// seg*16 + k/64. Per (l,bid): stage*WSTG + SWZ(tr*128 + kk*2), single fp16.
// seg0 = W_ih, seg1 = W_hh.
__global__ void convert_weights(const float* __restrict__ Wih,
                                const float* __restrict__ Whh) {
    unsigned gid = blockIdx.x * blockDim.x + threadIdx.x;   // < 2097152
    unsigned l    = gid >> 20;
    unsigned rest = gid & 0xFFFFF;
    unsigned seg  = rest >> 19;
    unsigned r2   = rest & 0x7FFFF;
    unsigned r    = r2 >> 7;            // weight row 0..4095
    unsigned k8   = r2 & 127;           // k block of 8

    const float* src = (seg ? Whh : Wih) + (size_t)l * 4096u * 1024u
                     + (size_t)r * 1024u + k8 * 8u;
    float4 v0 = ((const float4*)src)[0];
    float4 v1 = ((const float4*)src)[1];
    float vs[8] = {v0.x, v0.y, v0.z, v0.w, v1.x, v1.y, v1.z, v1.w};

    __half h[8];
#pragma unroll
    for (int e = 0; e < 8; e++) h[e] = __float2half(vs[e]);

    unsigned gate = r >> 10, u = r & 1023, bid = u >> 3, j = u & 7;
    unsigned tr = gate * 8 + j;
    unsigned k0 = k8 * 8, stg = seg * 16 + (k0 >> 6), kk = k0 & 63;
    unsigned off = SWZ(tr * 128 + kk * 2);                  // 16B aligned
    char* base = Wpack + ((size_t)(l * 128 + bid)) * CTA_WB + stg * WSTG;

    __half2 p0(h[0], h[1]), p1(h[2], h[3]), p2(h[4], h[5]), p3(h[6], h[7]);
    *(uint4*)(base + off) =
        make_uint4(*(uint32_t*)&p0, *(uint32_t*)&p1, *(uint32_t*)&p2, *(uint32_t*)&p3);
}

// ----------------- init: c, biases, initial activation packs -----------------
__global__ void init_misc(const float* __restrict__ x0, const float* __restrict__ h0,
                          const float* __restrict__ c0, const float* __restrict__ bih,
                          const float* __restrict__ bhh) {
    unsigned i = blockIdx.x * blockDim.x + threadIdx.x;     // 131072 threads
    if (i < 131072) ((float*)Cst)[i] = c0[i];
    if (i < 8192) {
        unsigned l = i >> 12, R = i & 4095;
        unsigned bid = R >> 5, rr = R & 31, gate = rr >> 3, j = rr & 7;
        unsigned u = bid * 8 + j;
        unsigned s = l * 4096 + gate * 1024 + u;
        Bpack[l][R] = bih[s] + bhh[s];
    }
    if (i < 3 * 8192) {                                     // activation packing
        unsigned m = i >> 13;                               // 0=Vx, 1=V0, 2=V1
        unsigned p = i & 8191;
        unsigned b = p >> 7, k8 = p & 127, k0 = k8 * 8;
        const float* src = (m == 0) ? (x0 + b * 1024 + k0)
                         : (h0 + (m - 1) * 65536 + b * 1024 + k0);
        char* buf = (m == 0) ? Vx : (m == 1 ? V0[0] : V1[0]);
        float4 v0 = ((const float4*)src)[0];
        float4 v1 = ((const float4*)src)[1];
        float vs[8] = {v0.x, v0.y, v0.z, v0.w, v1.x, v1.y, v1.z, v1.w};
        __half h[8];
#pragma unroll
        for (int e = 0; e < 8; e++) h[e] = __float2half(vs[e]);
        unsigned stg = k0 >> 6, kk = k0 & 63;
        unsigned off = SWZ(b * 128 + kk * 2);
        __half2 p0(h[0], h[1]), p1(h[2], h[3]), p2(h[4], h[5]), p3(h[6], h[7]);
        *(uint4*)(buf + stg * VSTG + off) =
            make_uint4(*(uint32_t*)&p0, *(uint32_t*)&p1, *(uint32_t*)&p2, *(uint32_t*)&p3);
    }
}

// ----------------- per (t, layer) fused step ---------------------------------
// CTA bid: units u = bid*8..+7, all gates, all 64 batches. M=32, N=64, K=2048.
// Warps 0-7 compute (each M16 x N16); warp 8 is the bulk-copy producer.
__global__ void __launch_bounds__(288, 1)
lstm_step_mma(int l, int t, float* __restrict__ out) {
    extern __shared__ __align__(1024) char smem[];
    uint32_t sb = smem_u32(smem);
    const int tid = threadIdx.x, wid = tid >> 5, lid = tid & 31;
    const int bid = blockIdx.x;

    // mbarriers: full[i] at sb + i*8 (tx), empty[i] at sb + 64 + i*8 (count 8)
    if (tid < NPIPE) MBAR_INIT(sb + tid * 8, 1);
    else if (tid < 2 * NPIPE) MBAR_INIT(sb + 64 + (tid - NPIPE) * 8, 8);
    __syncthreads();

    const char* Wc = Wpack + (size_t)(l * 128 + bid) * CTA_WB;
    const char* Vs0 = (l == 0) ? ((t == 0) ? Vx : V1[t & 1]) : V0[(t + 1) & 1];
    const char* Vs1 = (l == 0) ? V0[t & 1] : V1[t & 1];
    char*       Vdst = (l == 0) ? V0[(t + 1) & 1] : V1[(t + 1) & 1];
    const float* Bp = Bpack[l];
    float*       Cp = Cst[l];

    if (wid == 8) {
        // ---------------- producer warp ----------------
        if (lid == 0) {
            for (int s = 0; s < NSTAGES; s++) {
                const int slot = s & (NPIPE - 1);
                if (s >= NPIPE) MBAR_WAIT(sb + 64 + slot * 8, ((s >> 3) + 1) & 1);
                uint32_t fb = sb + slot * 8;
                MBAR_EXPECT_TX(fb, STGB);
                uint32_t sdst = sb + SMEM_ST0 + slot * STGB;
                const char* vsrc = ((s < 16) ? Vs0 : Vs1) + (size_t)(s & 15) * VSTG;
                BULK_G2S(sdst, Wc + (size_t)s * WSTG, WSTG, fb);
                BULK_G2S(sdst + WSTG, vsrc, VSTG, fb);
            }
        }
    } else {
        // ---------------- compute warps ----------------
        const int mgrp = wid & 1, ngrp = wid >> 1;
        const int mrow  = mgrp * 16;
        const int ncol0 = ngrp * 16;
        const int blk = lid >> 3, rin = lid & 7;
        const unsigned rbA = (unsigned)((mrow + (blk & 1) * 8 + rin) * 128 + (blk >> 1) * 16);
        const unsigned rbB = (unsigned)((ncol0 + (blk >> 1) * 8 + rin) * 128 + (blk & 1) * 16);

        float acc[2][4];
#pragma unroll
        for (int g = 0; g < 2; g++)
#pragma unroll
            for (int e = 0; e < 4; e++) acc[g][e] = 0.0f;

        for (int s = 0; s < NSTAGES; s++) {
            const int slot = s & (NPIPE - 1);
            MBAR_WAIT(sb + slot * 8, (s >> 3) & 1);
            const uint32_t wb = sb + SMEM_ST0 + slot * STGB;
            const uint32_t vb = wb + WSTG;
#pragma unroll
            for (int kc = 0; kc < 4; kc++) {
                uint32_t av[4], bv[4];
                const unsigned ko = kc * 32;
                ldmx4(av, wb + SWZ(rbA + ko));
                ldmx4(bv, vb + SWZ(rbB + ko));
                mma16816(acc[0], av, bv);       // 2 independent chains
                mma16816(acc[1], av, bv + 2);
            }
            if (lid == 0) MBAR_ARRIVE(sb + 64 + slot * 8);
        }

        // exchange fragments: gsm[row(32)][batch(64)]
        float* gsm = (float*)(smem + SMEM_GSM);
        const int gid = lid >> 2, tig = lid & 3;
#pragma unroll
        for (int g = 0; g < 2; g++) {
            const int col = ncol0 + g * 8 + tig * 2;
            const int r0 = mrow + gid, r1 = r0 + 8;
            gsm[r0 * GSM_STRIDE + col]     = acc[g][0];
            gsm[r0 * GSM_STRIDE + col + 1] = acc[g][1];
            gsm[r1 * GSM_STRIDE + col]     = acc[g][2];
            gsm[r1 * GSM_STRIDE + col + 1] = acc[g][3];
        }
    }
    __syncthreads();

    // ---- fused LSTM cell (first 256 threads; 512 items) ----------------------
    if (tid < 256) {
        float* gsm = (float*)(smem + SMEM_GSM);
#pragma unroll
        for (int q = 0; q < 2; q++) {
            const int p = tid + q * 256;             // 0..511
            const int b = p >> 3, j = p & 7;
            const int u = bid * 8 + j;
            float iv = gsm[(j)      * GSM_STRIDE + b] + Bp[bid * 32 + j];
            float fv = gsm[(8 + j)  * GSM_STRIDE + b] + Bp[bid * 32 + 8 + j];
            float gv = gsm[(16 + j) * GSM_STRIDE + b] + Bp[bid * 32 + 16 + j];
            float ov = gsm[(24 + j) * GSM_STRIDE + b] + Bp[bid * 32 + 24 + j];
            float cp = Cp[b * HID + u];
            float cn = sigm(fv) * cp + sigm(iv) * tanh_f(gv);
            float hn = sigm(ov) * tanh_f(cn);
            Cp[b * HID + u] = cn;
            if (l == 1) out[((size_t)b * LEN + t) * HID + u] = hn;
            char* vd = Vdst + (unsigned)(u >> 6) * VSTG;
            unsigned offd = SWZ((unsigned)(b * 128 + (u & 63) * 2));
            *(__half*)(vd + offd) = __float2half(hn);
        }
    }
}

extern "C" void kernel_launch(void* const* d_in, const int* in_sizes, int n_in,
                              void* d_out, int out_size) {
    const float* x0  = (const float*)d_in[0];   // [64,1,1024]
    const float* h0  = (const float*)d_in[1];   // [2,64,1024]
    const float* c0  = (const float*)d_in[2];   // [2,64,1024]
    const float* Wih = (const float*)d_in[3];   // [2,4096,1024]
    const float* Whh = (const float*)d_in[4];   // [2,4096,1024]
    const float* bih = (const float*)d_in[5];   // [2,4096]
    const float* bhh = (const float*)d_in[6];   // [2,4096]
    float* out = (float*)d_out;                 // [64,128,1024]

    cudaFuncSetAttribute(lstm_step_mma, cudaFuncAttributeMaxDynamicSharedMemorySize, SMEM_TOTAL);

    convert_weights<<<8192, 256>>>(Wih, Whh);
    init_misc<<<512, 256>>>(x0, h0, c0, bih, bhh);

    for (int t = 0; t < LEN; ++t) {
        lstm_step_mma<<<128, 288, SMEM_TOTAL>>>(0, t, out);
        lstm_step_mma<<<128, 288, SMEM_TOTAL>>>(1, t, out);
    }
}

// round 13
// speedup vs baseline: 1.5160x; 1.5160x over previous
#include <cuda_runtime.h>
#include <cuda_fp16.h>
#include <stdint.h>
#include <math.h>

#define BATCH 64
#define HID   1024
#define LEN   128

#define WPAN   4096            // W panel: 32 rows x 64 k fp16 (conversion unit)
#define VPAN   8192            // V panel: 64 rows x 64 k fp16 (conversion unit)
#define SSTG_W 8192            // per-stage W bytes (2 panels, K=128)
#define SSTG_V 16384           // per-stage V bytes (2 panels)
#define STGB   (SSTG_W + SSTG_V)   // 24576
#define NSTAGES 16             // K=2048 in 128-chunks (0-7: W_ih seg, 8-15: W_hh seg)
#define NPIPE  4
#define CTA_WB ((size_t)32 * WPAN)          // 128KB per (layer, cta)

#define SMEM_ST0 1024
#define SMEM_GSM (SMEM_ST0 + NPIPE * STGB)  // 99328
#define GSM_STRIDE 68
#define SMEM_TOTAL (SMEM_GSM + 32 * GSM_STRIDE * 4)   // 108032

#define SWZ(x) ((x) ^ (((x) >> 3) & 0x70))

// ----------------- persistent device state (no runtime allocations) ---------
__device__ __align__(1024) char Wpack[2u * 128u * 131072u];   // 32MB
__device__ __align__(1024) char Vx[16 * VPAN];
__device__ __align__(1024) char V0[2][16 * VPAN];
__device__ __align__(1024) char V1[2][16 * VPAN];
__device__ float Cst[2][BATCH * HID];
__device__ float Bpack[2][4096];

// ----------------- PTX helpers ----------------------------------------------
__device__ __forceinline__ uint32_t smem_u32(const void* p) {
    uint32_t a;
    asm("{ .reg .u64 t; cvta.to.shared.u64 t, %1; cvt.u32.u64 %0, t; }" : "=r"(a) : "l"(p));
    return a;
}
#define MBAR_INIT(a, c) asm volatile("mbarrier.init.shared.b64 [%0], %1;" :: "r"(a), "r"(c) : "memory")
#define MBAR_EXPECT_TX(a, tx) asm volatile("mbarrier.arrive.expect_tx.shared.b64 _, [%0], %1;" :: "r"(a), "r"(tx) : "memory")
#define MBAR_ARRIVE(a) asm volatile("mbarrier.arrive.shared.b64 _, [%0];" :: "r"(a) : "memory")
#define MBAR_WAIT(addr, ph) do {                                              \
    uint32_t _m = (addr), _p = (ph), _d;                                      \
    asm volatile("{\n\t.reg .pred p;\n\t"                                     \
        "mbarrier.try_wait.parity.acquire.cta.shared::cta.b64 p, [%1], %2;\n\t" \
        "selp.b32 %0, 1, 0, p;\n\t}" : "=r"(_d) : "r"(_m), "r"(_p) : "memory"); \
    if (!_d) {                                                                \
        asm volatile("{\n\t.reg .pred P1;\n\t"                                \
            "WL%=:\n\t"                                                       \
            "mbarrier.try_wait.parity.acquire.cta.shared::cta.b64 P1, [%0], %1, 0x989680;\n\t" \
            "@P1 bra.uni WD%=;\n\t"                                           \
            "bra.uni WL%=;\n\t"                                               \
            "WD%=:\n\t}" :: "r"(_m), "r"(_p) : "memory");                     \
    } } while (0)

#define BULK_G2S(dst, src, bytes, mbar)                                       \
    asm volatile("cp.async.bulk.shared::cta.global.mbarrier::complete_tx::bytes [%0], [%1], %2, [%3];" \
        :: "r"(dst), "l"(src), "r"(bytes), "r"(mbar) : "memory")

__device__ __forceinline__ void ldmx4(uint32_t* r, uint32_t addr) {
    asm volatile("ldmatrix.sync.aligned.m8n8.x4.shared.b16 {%0,%1,%2,%3}, [%4];"
        : "=r"(r[0]), "=r"(r[1]), "=r"(r[2]), "=r"(r[3]) : "r"(addr));
}
__device__ __forceinline__ void mma16816(float* d, const uint32_t* a, const uint32_t* b) {
    asm volatile("mma.sync.aligned.m16n8k16.row.col.f32.f16.f16.f32 "
        "{%0,%1,%2,%3}, {%4,%5,%6,%7}, {%8,%9}, {%0,%1,%2,%3};"
        : "+f"(d[0]), "+f"(d[1]), "+f"(d[2]), "+f"(d[3])
        : "r"(a[0]), "r"(a[1]), "r"(a[2]), "r"(a[3]), "r"(b[0]), "r"(b[1]));
}
__device__ __forceinline__ float sigm(float x) { return 1.0f / (1.0f + __expf(-x)); }
__device__ __forceinline__ float tanh_f(float x) {
    float ax = fabsf(x);
    float t  = __expf(-2.0f * ax);
    return copysignf((1.0f - t) / (1.0f + t), x);
}

// ----------------- one-time (per replay) weight packing ----------------------
// CTA bid owns units u = bid*8+j; tile row tr = gate*8+j (32 rows). Panel =
// seg*16 + k/64. Per (l,bid): panel*WPAN + SWZ(tr*128 + kk*2), single fp16.
__global__ void convert_weights(const float* __restrict__ Wih,
                                const float* __restrict__ Whh) {
    unsigned gid = blockIdx.x * blockDim.x + threadIdx.x;   // < 2097152
    unsigned l    = gid >> 20;
    unsigned rest = gid & 0xFFFFF;
    unsigned seg  = rest >> 19;
    unsigned r2   = rest & 0x7FFFF;
    unsigned r    = r2 >> 7;            // weight row 0..4095
    unsigned k8   = r2 & 127;           // k block of 8

    const float* src = (seg ? Whh : Wih) + (size_t)l * 4096u * 1024u
                     + (size_t)r * 1024u + k8 * 8u;
    float4 v0 = ((const float4*)src)[0];
    float4 v1 = ((const float4*)src)[1];
    float vs[8] = {v0.x, v0.y, v0.z, v0.w, v1.x, v1.y, v1.z, v1.w};

    __half h[8];
#pragma unroll
    for (int e = 0; e < 8; e++) h[e] = __float2half(vs[e]);

    unsigned gate = r >> 10, u = r & 1023, bid = u >> 3, j = u & 7;
    unsigned tr = gate * 8 + j;
    unsigned k0 = k8 * 8, pan = seg * 16 + (k0 >> 6), kk = k0 & 63;
    unsigned off = SWZ(tr * 128 + kk * 2);                  // 16B aligned
    char* base = Wpack + ((size_t)(l * 128 + bid)) * CTA_WB + pan * WPAN;

    __half2 p0(h[0], h[1]), p1(h[2], h[3]), p2(h[4], h[5]), p3(h[6], h[7]);
    *(uint4*)(base + off) =
        make_uint4(*(uint32_t*)&p0, *(uint32_t*)&p1, *(uint32_t*)&p2, *(uint32_t*)&p3);
}

// ----------------- init: c, biases, initial activation packs -----------------
__global__ void init_misc(const float* __restrict__ x0, const float* __restrict__ h0,
                          const float* __restrict__ c0, const float* __restrict__ bih,
                          const float* __restrict__ bhh) {
    unsigned i = blockIdx.x * blockDim.x + threadIdx.x;     // 131072 threads
    if (i < 131072) ((float*)Cst)[i] = c0[i];
    if (i < 8192) {
        unsigned l = i >> 12, R = i & 4095;
        unsigned bid = R >> 5, rr = R & 31, gate = rr >> 3, j = rr & 7;
        unsigned u = bid * 8 + j;
        unsigned s = l * 4096 + gate * 1024 + u;
        Bpack[l][R] = bih[s] + bhh[s];
    }
    if (i < 3 * 8192) {                                     // activation packing
        unsigned m = i >> 13;                               // 0=Vx, 1=V0, 2=V1
        unsigned p = i & 8191;
        unsigned b = p >> 7, k8 = p & 127, k0 = k8 * 8;
        const float* src = (m == 0) ? (x0 + b * 1024 + k0)
                         : (h0 + (m - 1) * 65536 + b * 1024 + k0);
        char* buf = (m == 0) ? Vx : (m == 1 ? V0[0] : V1[0]);
        float4 v0 = ((const float4*)src)[0];
        float4 v1 = ((const float4*)src)[1];
        float vs[8] = {v0.x, v0.y, v0.z, v0.w, v1.x, v1.y, v1.z, v1.w};
        __half h[8];
#pragma unroll
        for (int e = 0; e < 8; e++) h[e] = __float2half(vs[e]);
        unsigned pan = k0 >> 6, kk = k0 & 63;
        unsigned off = SWZ(b * 128 + kk * 2);
        __half2 p0(h[0], h[1]), p1(h[2], h[3]), p2(h[4], h[5]), p3(h[6], h[7]);
        *(uint4*)(buf + pan * VPAN + off) =
            make_uint4(*(uint32_t*)&p0, *(uint32_t*)&p1, *(uint32_t*)&p2, *(uint32_t*)&p3);
    }
}

// ----------------- per (t, layer) fused step ---------------------------------
// CTA bid: units u = bid*8..+7, all gates, all 64 batches. M=32, N=64, K=2048.
// Warps 0-7 compute (each M16 x N16); warp 8 is the bulk-copy producer.
// Stage = K=128 (two contiguous 64-k panels). 16 stages, NPIPE=4.
__global__ void __launch_bounds__(288, 1)
lstm_step_mma(int l, int t, float* __restrict__ out) {
    extern __shared__ __align__(1024) char smem[];
    uint32_t sb = smem_u32(smem);
    const int tid = threadIdx.x, wid = tid >> 5, lid = tid & 31;
    const int bid = blockIdx.x;

    // mbarriers: full[i] at sb + i*8 (tx), empty[i] at sb + 64 + i*8 (count 8)
    if (tid < NPIPE) MBAR_INIT(sb + tid * 8, 1);
    else if (tid < 2 * NPIPE) MBAR_INIT(sb + 64 + (tid - NPIPE) * 8, 8);
    __syncthreads();

    const char* Wc = Wpack + (size_t)(l * 128 + bid) * CTA_WB;
    const char* Vs0 = (l == 0) ? ((t == 0) ? Vx : V1[t & 1]) : V0[(t + 1) & 1];
    const char* Vs1 = (l == 0) ? V0[t & 1] : V1[t & 1];
    char*       Vdst = (l == 0) ? V0[(t + 1) & 1] : V1[(t + 1) & 1];
    const float* Bp = Bpack[l];
    float*       Cp = Cst[l];

    if (wid == 8) {
        // ---------------- producer warp ----------------
        if (lid == 0) {
            for (int s = 0; s < NSTAGES; s++) {
                const int slot = s & (NPIPE - 1);
                if (s >= NPIPE) MBAR_WAIT(sb + 64 + slot * 8, ((s >> 2) + 1) & 1);
                uint32_t fb = sb + slot * 8;
                MBAR_EXPECT_TX(fb, STGB);
                uint32_t sdst = sb + SMEM_ST0 + slot * STGB;
                const char* vsrc = (s < 8) ? (Vs0 + (size_t)s * SSTG_V)
                                           : (Vs1 + (size_t)(s - 8) * SSTG_V);
                BULK_G2S(sdst, Wc + (size_t)s * SSTG_W, SSTG_W, fb);
                BULK_G2S(sdst + SSTG_W, vsrc, SSTG_V, fb);
            }
        }
    } else {
        // ---------------- compute warps ----------------
        const int mgrp = wid & 1, ngrp = wid >> 1;
        const int mrow  = mgrp * 16;
        const int ncol0 = ngrp * 16;
        const int blk = lid >> 3, rin = lid & 7;
        const unsigned rbA = (unsigned)((mrow + (blk & 1) * 8 + rin) * 128 + (blk >> 1) * 16);
        const unsigned rbB = (unsigned)((ncol0 + (blk >> 1) * 8 + rin) * 128 + (blk & 1) * 16);

        // 4 independent accumulator chains: [parity][n8-group]
        float acc[2][2][4];
#pragma unroll
        for (int p = 0; p < 2; p++)
#pragma unroll
            for (int g = 0; g < 2; g++)
#pragma unroll
                for (int e = 0; e < 4; e++) acc[p][g][e] = 0.0f;

        for (int s = 0; s < NSTAGES; s++) {
            const int slot = s & (NPIPE - 1);
            MBAR_WAIT(sb + slot * 8, (s >> 2) & 1);
            const uint32_t wb = sb + SMEM_ST0 + slot * STGB;
            const uint32_t vb = wb + SSTG_W;
#pragma unroll
            for (int h = 0; h < 2; h++) {                 // two 64-k panels
                const uint32_t wbh = wb + h * WPAN;
                const uint32_t vbh = vb + h * VPAN;
#pragma unroll
                for (int kc = 0; kc < 4; kc++) {
                    uint32_t av[4], bv[4];
                    const unsigned ko = kc * 32;
                    ldmx4(av, wbh + SWZ(rbA + ko));
                    ldmx4(bv, vbh + SWZ(rbB + ko));
                    mma16816(acc[kc & 1][0], av, bv);
                    mma16816(acc[kc & 1][1], av, bv + 2);
                }
            }
            if (lid == 0) MBAR_ARRIVE(sb + 64 + slot * 8);
        }

        // exchange fragments: gsm[row(32)][batch(64)]
        float* gsm = (float*)(smem + SMEM_GSM);
        const int gid = lid >> 2, tig = lid & 3;
#pragma unroll
        for (int g = 0; g < 2; g++) {
            const int col = ncol0 + g * 8 + tig * 2;
            const int r0 = mrow + gid, r1 = r0 + 8;
            gsm[r0 * GSM_STRIDE + col]     = acc[0][g][0] + acc[1][g][0];
            gsm[r0 * GSM_STRIDE + col + 1] = acc[0][g][1] + acc[1][g][1];
            gsm[r1 * GSM_STRIDE + col]     = acc[0][g][2] + acc[1][g][2];
            gsm[r1 * GSM_STRIDE + col + 1] = acc[0][g][3] + acc[1][g][3];
        }
    }
    __syncthreads();

    // ---- fused LSTM cell (first 256 threads; 512 items) ----------------------
    if (tid < 256) {
        float* gsm = (float*)(smem + SMEM_GSM);
#pragma unroll
        for (int q = 0; q < 2; q++) {
            const int p = tid + q * 256;             // 0..511
            const int b = p >> 3, j = p & 7;
            const int u = bid * 8 + j;
            float iv = gsm[(j)      * GSM_STRIDE + b] + Bp[bid * 32 + j];
            float fv = gsm[(8 + j)  * GSM_STRIDE + b] + Bp[bid * 32 + 8 + j];
            float gv = gsm[(16 + j) * GSM_STRIDE + b] + Bp[bid * 32 + 16 + j];
            float ov = gsm[(24 + j) * GSM_STRIDE + b] + Bp[bid * 32 + 24 + j];
            float cp = Cp[b * HID + u];
            float cn = sigm(fv) * cp + sigm(iv) * tanh_f(gv);
            float hn = sigm(ov) * tanh_f(cn);
            Cp[b * HID + u] = cn;
            if (l == 1) out[((size_t)b * LEN + t) * HID + u] = hn;
            char* vd = Vdst + (unsigned)(u >> 6) * VPAN;
            unsigned offd = SWZ((unsigned)(b * 128 + (u & 63) * 2));
            *(__half*)(vd + offd) = __float2half(hn);
        }
    }
}

extern "C" void kernel_launch(void* const* d_in, const int* in_sizes, int n_in,
                              void* d_out, int out_size) {
    const float* x0  = (const float*)d_in[0];   // [64,1,1024]
    const float* h0  = (const float*)d_in[1];   // [2,64,1024]
    const float* c0  = (const float*)d_in[2];   // [2,64,1024]
    const float* Wih = (const float*)d_in[3];   // [2,4096,1024]
    const float* Whh = (const float*)d_in[4];   // [2,4096,1024]
    const float* bih = (const float*)d_in[5];   // [2,4096]
    const float* bhh = (const float*)d_in[6];   // [2,4096]
    float* out = (float*)d_out;                 // [64,128,1024]

    cudaFuncSetAttribute(lstm_step_mma, cudaFuncAttributeMaxDynamicSharedMemorySize, SMEM_TOTAL);

    convert_weights<<<8192, 256>>>(Wih, Whh);
    init_misc<<<512, 256>>>(x0, h0, c0, bih, bhh);

    for (int t = 0; t < LEN; ++t) {
        lstm_step_mma<<<128, 288, SMEM_TOTAL>>>(0, t, out);
        lstm_step_mma<<<128, 288, SMEM_TOTAL>>>(1, t, out);
    }
}